// round 10
// baseline (speedup 1.0000x reference)
#include <cuda_runtime.h>
#include <cstdint>

#define HW    65536
#define NQ    100
#define NT    32
#define NB    8
#define NROWP 112   // 7 mtiles * 16
#define NKT   4096  // k-tiles per batch (HW/16)

// ---------------- device scratch ----------------
__device__ uint4    g_bfrag[NB * NKT * 32 * 2];  // precomputed MMA B-fragments
__device__ float    g_tsum[NB * NT];
__device__ float    g_dotPM[NB * NROWP * NT];
__device__ float    g_dotSIG[NB * NROWP * NT];
__device__ float    g_sumSP[NB * NROWP];
__device__ float    g_sumSIG[NB * NROWP];
__device__ float    g_classT[NB * NT * NQ];      // [b][t][n]

// ---------------- helpers ----------------
__device__ __forceinline__ uint32_t pack_bf16(float hi, float lo) {
    uint32_t d;
    asm("cvt.rn.bf16x2.f32 %0, %1, %2;" : "=r"(d) : "f"(hi), "f"(lo));
    return d;
}

__device__ __forceinline__ void mma_bf16(float* c, const uint32_t* a,
                                         uint32_t b0, uint32_t b1) {
    asm volatile(
        "mma.sync.aligned.m16n8k16.row.col.f32.bf16.bf16.f32 "
        "{%0,%1,%2,%3}, {%4,%5,%6,%7}, {%8,%9}, {%0,%1,%2,%3};"
        : "+f"(c[0]), "+f"(c[1]), "+f"(c[2]), "+f"(c[3])
        : "r"(a[0]), "r"(a[1]), "r"(a[2]), "r"(a[3]), "r"(b0), "r"(b1));
}

__device__ __forceinline__ uint32_t fkey(float f) {
    uint32_t u = __float_as_uint(f);
    return (u & 0x80000000u) ? ~u : (u | 0x80000000u);
}
__device__ __forceinline__ float fkey_inv(uint32_t k) {
    uint32_t u = (k & 0x80000000u) ? (k ^ 0x80000000u) : ~k;
    return __uint_as_float(u);
}
__device__ __forceinline__ int sel4i(int a0, int a1, int a2, int a3, int s) {
    return s == 0 ? a0 : s == 1 ? a1 : s == 2 ? a2 : a3;
}

// ---------------- kernel 1: class cost (+ accumulator zeroing) ----------------
__global__ void k_class(const float* __restrict__ logits,
                        const int* __restrict__ labels) {
    int gid = blockIdx.x * 32 + threadIdx.x;
    for (int i = gid; i < NB * NROWP * NT; i += NB * NQ * 32) {
        g_dotPM[i] = 0.f; g_dotSIG[i] = 0.f;
    }
    if (gid < NB * NROWP) { g_sumSP[gid] = 0.f; g_sumSIG[gid] = 0.f; }
    if (gid < NB * NT)    { g_tsum[gid] = 0.f; }

    int b = blockIdx.x / NQ, n = blockIdx.x % NQ;
    int lane = threadIdx.x;
    __shared__ float sh[81];
    const float* L = logits + (size_t)(b * NQ + n) * 81;

    float x0 = L[lane];
    float x1 = (lane + 32 < 81) ? L[lane + 32] : -1e30f;
    float x2 = (lane + 64 < 81) ? L[lane + 64] : -1e30f;
    float m = fmaxf(x0, fmaxf(x1, x2));
    #pragma unroll
    for (int o = 16; o; o >>= 1) m = fmaxf(m, __shfl_xor_sync(0xffffffffu, m, o));

    float e0 = __expf(x0 - m);
    float e1 = (lane + 32 < 81) ? __expf(x1 - m) : 0.f;
    float e2 = (lane + 64 < 81) ? __expf(x2 - m) : 0.f;
    float s = e0 + e1 + e2;
    #pragma unroll
    for (int o = 16; o; o >>= 1) s += __shfl_xor_sync(0xffffffffu, s, o);

    sh[lane] = e0;
    if (lane + 32 < 81) sh[lane + 32] = e1;
    if (lane + 64 < 81) sh[lane + 64] = e2;
    __syncwarp();

    float inv = 1.0f / s;
    int lbl = labels[b * NT + lane];
    g_classT[(b * NT + lane) * NQ + n] = -sh[lbl] * inv;
}

// ---------------- kernel 2: target masks -> sums + B-fragments ----------------
__global__ __launch_bounds__(256) void k_tmask(const float* __restrict__ tgt) {
    __shared__ uint32_t sbits[512];
    const int b = blockIdx.y;
    const int tid = threadIdx.x;
    int p0 = blockIdx.x * 512 + tid * 2;
    int h = p0 >> 8, w = p0 & 255;
    size_t base = ((size_t)b * NT) * 262144 + (size_t)(2 * h) * 512 + 2 * w;
    uint32_t w0 = 0, w1 = 0;
    #pragma unroll
    for (int t = 0; t < 32; ++t) {
        float4 v = __ldcs((const float4*)(tgt + base + (size_t)t * 262144));
        w0 |= (uint32_t)(v.x != 0.0f) << t;
        w1 |= (uint32_t)(v.z != 0.0f) << t;
    }
    sbits[tid * 2]     = w0;
    sbits[tid * 2 + 1] = w1;

    int lane = tid & 31;
    int cnt = 0;
    #pragma unroll
    for (int t = 0; t < 32; ++t) {
        unsigned m0 = __ballot_sync(0xffffffffu, (w0 >> t) & 1u);
        unsigned m1 = __ballot_sync(0xffffffffu, (w1 >> t) & 1u);
        if (lane == t) cnt = __popc(m0) + __popc(m1);
    }
    atomicAdd(&g_tsum[b * NT + lane], (float)cnt);
    __syncthreads();

    const int warp = tid >> 5;
    const int kq = (lane & 3) << 1, rq = lane >> 2;
    #pragma unroll
    for (int i = 0; i < 4; ++i) {
        int ktl = warp * 4 + i;
        uint32_t t0 = sbits[ktl * 16 + kq]     >> rq;
        uint32_t t1 = sbits[ktl * 16 + kq + 1] >> rq;
        uint32_t t2 = sbits[ktl * 16 + kq + 8] >> rq;
        uint32_t t3 = sbits[ktl * 16 + kq + 9] >> rq;
        uint4 lo, hi;
        lo.x = ((t0 & 1u) * 0x3F80u)         | ((t1 & 1u) * 0x3F800000u);
        lo.y = ((t2 & 1u) * 0x3F80u)         | ((t3 & 1u) * 0x3F800000u);
        lo.z = (((t0 >> 8) & 1u) * 0x3F80u)  | (((t1 >> 8) & 1u) * 0x3F800000u);
        lo.w = (((t2 >> 8) & 1u) * 0x3F80u)  | (((t3 >> 8) & 1u) * 0x3F800000u);
        hi.x = (((t0 >> 16) & 1u) * 0x3F80u) | (((t1 >> 16) & 1u) * 0x3F800000u);
        hi.y = (((t2 >> 16) & 1u) * 0x3F80u) | (((t3 >> 16) & 1u) * 0x3F800000u);
        hi.z = (((t0 >> 24) & 1u) * 0x3F80u) | (((t1 >> 24) & 1u) * 0x3F800000u);
        hi.w = (((t2 >> 24) & 1u) * 0x3F80u) | (((t3 >> 24) & 1u) * 0x3F800000u);
        int kt = blockIdx.x * 32 + ktl;
        uint4* dst = g_bfrag + ((size_t)(b * NKT + kt) * 32 + lane) * 2;
        dst[0] = lo;
        dst[1] = hi;
    }
}

// ---------------- kernel 3: bf16x2 elementwise + MMA, block-reduced flush ----
__global__ __launch_bounds__(256) void k_main(const float* __restrict__ pm) {
    __shared__ float sPM[16 * 32];
    __shared__ float sSG[16 * 32];
    __shared__ float sSP[16];
    __shared__ float sSS[16];

    const int b = blockIdx.z, mt = blockIdx.y;
    const int tid = threadIdx.x;
    const int warp = tid >> 5, lane = tid & 31;
    const int kstart = blockIdx.x * (HW / 8) + warp * (HW / 8 / 8);  // 1024 px/warp
    const int rq = lane >> 2;
    const int kq = (lane & 3) << 1;
    const int r_lo = mt * 16 + rq, r_hi = r_lo + 8;
    const int rl = min(r_lo, NQ - 1), rh = min(r_hi, NQ - 1);

    for (int i = tid; i < 512; i += 256) { sPM[i] = 0.f; sSG[i] = 0.f; }
    if (tid < 16) { sSP[tid] = 0.f; sSS[tid] = 0.f; }
    __syncthreads();

    const float* pmb = pm + (size_t)b * NQ * HW;
    const uint4* bf  = g_bfrag + ((size_t)(b * NKT + (kstart >> 4)) * 32 + lane) * 2;

    const uint32_t HALF2  = 0x3F003F00u;  // bf16x2 (0.5, 0.5)
    const uint32_t NHALF2 = 0xBF00BF00u;  // bf16x2 (-0.5, -0.5)
    const uint32_t ONES2  = 0x3F803F80u;  // bf16x2 (1.0, 1.0)

    float cpm[4][4], csg[4][4], csum[4];
    #pragma unroll
    for (int i = 0; i < 4; ++i) {
        csum[i] = 0.f;
        #pragma unroll
        for (int j = 0; j < 4; ++j) { cpm[i][j] = 0.f; csg[i][j] = 0.f; }
    }
    float splog0 = 0.f, splog1 = 0.f;

    #pragma unroll 2
    for (int it = 0; it < 64; ++it) {
        int k0 = kstart + it * 16 + kq;
        float2 x00 = __ldcs((const float2*)(pmb + (size_t)rl * HW + k0));
        float2 x10 = __ldcs((const float2*)(pmb + (size_t)rh * HW + k0));
        float2 x01 = __ldcs((const float2*)(pmb + (size_t)rl * HW + k0 + 8));
        float2 x11 = __ldcs((const float2*)(pmb + (size_t)rh * HW + k0 + 8));
        uint4 blo = bf[it * 64];
        uint4 bhi = bf[it * 64 + 1];

        uint32_t apm[4] = { pack_bf16(x00.y, x00.x), pack_bf16(x10.y, x10.x),
                            pack_bf16(x01.y, x01.x), pack_bf16(x11.y, x11.x) };

        uint32_t asg[4], aq[4];
        #pragma unroll
        for (int q = 0; q < 4; ++q) {
            uint32_t th;
            asm("mul.rn.bf16x2 %0, %1, %2;" : "=r"(th) : "r"(apm[q]), "r"(HALF2));
            asm("tanh.approx.bf16x2 %0, %1;" : "=r"(th) : "r"(th));
            asm("fma.rn.bf16x2 %0, %1, %2, %3;" : "=r"(asg[q]) : "r"(th), "r"(HALF2),  "r"(HALF2));
            asm("fma.rn.bf16x2 %0, %1, %2, %3;" : "=r"(aq[q])  : "r"(th), "r"(NHALF2), "r"(HALF2));
        }

        uint32_t prL, prH;
        asm("mul.rn.bf16x2 %0, %1, %2;" : "=r"(prL) : "r"(aq[0]), "r"(aq[2]));
        asm("mul.rn.bf16x2 %0, %1, %2;" : "=r"(prH) : "r"(aq[1]), "r"(aq[3]));
        float fL = __uint_as_float(prL << 16) * __uint_as_float(prL & 0xFFFF0000u);
        float fH = __uint_as_float(prH << 16) * __uint_as_float(prH & 0xFFFF0000u);
        splog0 += __logf(fL);
        splog1 += __logf(fH);

        mma_bf16(cpm[0], apm, blo.x, blo.y);
        mma_bf16(csg[0], asg, blo.x, blo.y);
        mma_bf16(cpm[1], apm, blo.z, blo.w);
        mma_bf16(csg[1], asg, blo.z, blo.w);
        mma_bf16(cpm[2], apm, bhi.x, bhi.y);
        mma_bf16(csg[2], asg, bhi.x, bhi.y);
        mma_bf16(cpm[3], apm, bhi.z, bhi.w);
        mma_bf16(csg[3], asg, bhi.z, bhi.w);
        mma_bf16(csum,   asg, ONES2, ONES2);
    }

    // block-level reduction in shared, then one global flush per cell
    #pragma unroll
    for (int nt = 0; nt < 4; ++nt) {
        int c = nt * 8 + kq;
        atomicAdd(&sPM[rq * 32 + c],           cpm[nt][0]);
        atomicAdd(&sPM[rq * 32 + c + 1],       cpm[nt][1]);
        atomicAdd(&sPM[(rq + 8) * 32 + c],     cpm[nt][2]);
        atomicAdd(&sPM[(rq + 8) * 32 + c + 1], cpm[nt][3]);
        atomicAdd(&sSG[rq * 32 + c],           csg[nt][0]);
        atomicAdd(&sSG[rq * 32 + c + 1],       csg[nt][1]);
        atomicAdd(&sSG[(rq + 8) * 32 + c],     csg[nt][2]);
        atomicAdd(&sSG[(rq + 8) * 32 + c + 1], csg[nt][3]);
    }
    atomicAdd(&sSP[rq],     -splog0);
    atomicAdd(&sSP[rq + 8], -splog1);
    if (kq == 0) {  // csum cols identical; one lane per quad
        atomicAdd(&sSS[rq],     csum[0]);
        atomicAdd(&sSS[rq + 8], csum[2]);
    }
    __syncthreads();

    for (int i = tid; i < 512; i += 256) {
        int r = i >> 5, c = i & 31;
        int grow = mt * 16 + r;
        atomicAdd(&g_dotPM[(b * NROWP + grow) * NT + c],  sPM[i]);
        atomicAdd(&g_dotSIG[(b * NROWP + grow) * NT + c], sSG[i]);
    }
    if (tid < 16) {
        int grow = mt * 16 + tid;
        atomicAdd(&g_sumSP[b * NROWP + grow],  sSP[tid]);
        atomicAdd(&g_sumSIG[b * NROWP + grow], sSS[tid]);
    }
}

// ---------------- kernel 4: cost assembly + JV (greedy init, deferred duals) --
__global__ void k_hung(float* __restrict__ out) {
    const int b = blockIdx.x;
    const int lane = threadIdx.x;
    __shared__ float Cs[NT * NQ];
    __shared__ float u[NT + 1];
    __shared__ int   psh[NQ + 1];

    for (int idx = lane; idx < NT * NQ; idx += 32) {
        int t = idx / NQ, n = idx - t * NQ;
        float spm  = g_sumSP[b * NROWP + n] * (1.0f / HW);
        float dpm  = g_dotPM[(b * NROWP + n) * NT + t] * (1.0f / HW);
        float dsg  = g_dotSIG[(b * NROWP + n) * NT + t];
        float den  = g_sumSIG[b * NROWP + n] + g_tsum[b * NT + t] + 1.0f;
        float dice = 1.0f - __fdividef(2.0f * dsg + 1.0f, den);
        Cs[idx] = g_classT[b * NT * NQ + idx] + (spm - dpm) + dice;
    }
    __syncwarp();

    float v0 = 0.f, v1 = 0.f, v2 = 0.f, v3 = 0.f;
    int   p0 = 0, p1 = 0, p2 = 0, p3 = 0;
    int   w0 = 0, w1 = 0, w2 = 0, w3 = 0;

    // ---- greedy init: row reduction + tight-arc matching ----
    uint32_t cm0 = 1u, cm1 = 0, cm2 = 0, cm3 = 0;
    uint32_t freerows = 0;
    for (int i = 1; i <= NT; ++i) {
        const float* Crow = Cs + (i - 1) * NQ;
        uint32_t bk = 0xFFFFFFFFu;
        if (lane >= 1) { uint32_t k = (fkey(Crow[lane - 1]) & ~127u) | lane;         if (k < bk) bk = k; }
        {               uint32_t k = (fkey(Crow[31 + lane]) & ~127u) | (32 + lane);  if (k < bk) bk = k; }
        {               uint32_t k = (fkey(Crow[63 + lane]) & ~127u) | (64 + lane);  if (k < bk) bk = k; }
        if (lane <= 4) { uint32_t k = (fkey(Crow[95 + lane]) & ~127u) | (96 + lane); if (k < bk) bk = k; }
        uint32_t kmin = __reduce_min_sync(0xffffffffu, bk);
        int js = kmin & 127;
        u[i] = fkey_inv(kmin & ~127u);     // floor => dual-feasible
        int slot = js >> 5;
        uint32_t bit = 1u << (js & 31);
        bool taken = (slot == 0 ? cm0 : slot == 1 ? cm1 : slot == 2 ? cm2 : cm3) & bit;
        if (!taken) {
            if ((js & 31) == lane) {
                if (slot == 0) p0 = i; else if (slot == 1) p1 = i;
                else if (slot == 2) p2 = i; else p3 = i;
            }
            if (slot == 0) cm0 |= bit; else if (slot == 1) cm1 |= bit;
            else if (slot == 2) cm2 |= bit; else cm3 |= bit;
        } else {
            freerows |= 1u << (i - 1);
        }
    }
    __syncwarp();

    // ---- Dijkstra phases with deferred dual updates (classical LAPJV) ----
    while (freerows) {
        int i = __ffs(freerows);
        freerows &= freerows - 1;
        // d = absolute shortest-path distance; slot0 of lane0 is virtual col 0 (d=0)
        float d0 = (lane == 0) ? 0.f : 1e30f, d1 = 1e30f, d2 = 1e30f, d3 = 1e30f;
        unsigned usedm = 0;
        if (lane == 0) p0 = i;             // p[0] = entering free row
        float mu = 0.f;
        int j0 = 0, i0 = i;

        while (true) {
            if ((j0 & 31) == lane) usedm |= 1u << (j0 >> 5);
            float s = mu - u[i0];
            const float* Crow = Cs + (i0 - 1) * NQ;

            uint32_t bk = 0xFFFFFFFFu; int bp = 0;
            if (lane >= 1 && !(usedm & 1u)) {
                float alt = (Crow[lane - 1] - v0) + s;
                if (alt < d0) { d0 = alt; w0 = j0; }
                uint32_t k = fkey(d0);
                if (k < bk) { bk = k; bp = lane | (p0 << 8); }
            }
            if (!(usedm & 2u)) {
                float alt = (Crow[31 + lane] - v1) + s;
                if (alt < d1) { d1 = alt; w1 = j0; }
                uint32_t k = fkey(d1);
                if (k < bk) { bk = k; bp = (32 + lane) | (p1 << 8); }
            }
            if (!(usedm & 4u)) {
                float alt = (Crow[63 + lane] - v2) + s;
                if (alt < d2) { d2 = alt; w2 = j0; }
                uint32_t k = fkey(d2);
                if (k < bk) { bk = k; bp = (64 + lane) | (p2 << 8); }
            }
            if (lane <= 4 && !(usedm & 8u)) {
                float alt = (Crow[95 + lane] - v3) + s;
                if (alt < d3) { d3 = alt; w3 = j0; }
                uint32_t k = fkey(d3);
                if (k < bk) { bk = k; bp = (96 + lane) | (p3 << 8); }
            }

            uint32_t kmin = __reduce_min_sync(0xffffffffu, bk);
            unsigned ball = __ballot_sync(0xffffffffu, bk == kmin);
            int src = __ffs(ball) - 1;
            int packed = __shfl_sync(0xffffffffu, bp, src);
            mu = fkey_inv(kmin);
            j0 = packed & 0xFF;
            int pj0 = packed >> 8;
            if (pj0 == 0) break;
            i0 = pj0;
        }

        // deferred dual update (uses PRE-augment p): u[p[j]] += mu - d[j]; v[j] -= mu - d[j]
        if (usedm & 1u) { float adj = mu - d0; v0 -= adj; u[p0] += adj; }
        if (usedm & 2u) { float adj = mu - d1; v1 -= adj; u[p1] += adj; }
        if (usedm & 4u) { float adj = mu - d2; v2 -= adj; u[p2] += adj; }
        if (usedm & 8u) { float adj = mu - d3; v3 -= adj; u[p3] += adj; }
        __syncwarp();

        // augment along pred chain
        while (j0 != 0) {
            int j1  = __shfl_sync(0xffffffffu, sel4i(w0, w1, w2, w3, j0 >> 5), j0 & 31);
            int pj1 = __shfl_sync(0xffffffffu, sel4i(p0, p1, p2, p3, j1 >> 5), j1 & 31);
            if ((j0 & 31) == lane) {
                int s = j0 >> 5;
                if (s == 0) p0 = pj1; else if (s == 1) p1 = pj1;
                else if (s == 2) p2 = pj1; else p3 = pj1;
            }
            j0 = j1;
        }
        __syncwarp();
    }

    psh[lane] = p0;
    psh[32 + lane] = p1;
    psh[64 + lane] = p2;
    if (lane <= 4) psh[96 + lane] = p3;
    __syncwarp();

    if (lane == 0) {
        int k = 0;
        for (int j = 1; j <= NQ; ++j) {
            if (psh[j]) {
                out[b * NT + k]           = (float)(j - 1);
                out[NB * NT + b * NT + k] = (float)(psh[j] - 1);
                ++k;
            }
        }
    }
}

// ---------------- launch ----------------
extern "C" void kernel_launch(void* const* d_in, const int* in_sizes, int n_in,
                              void* d_out, int out_size) {
    const float* logits = nullptr;
    const float* pmask  = nullptr;
    const float* tmask  = nullptr;
    const int*   labels = nullptr;

    for (int i = 0; i < n_in; ++i) {
        switch (in_sizes[i]) {
            case 64800:    logits = (const float*)d_in[i]; break;
            case 52428800: pmask  = (const float*)d_in[i]; break;
            case 256:      labels = (const int*)d_in[i];   break;
            default:
                if (in_sizes[i] == 67108864) tmask = (const float*)d_in[i];
                break;
        }
    }
    float* out = (float*)d_out;

    k_class<<<NB * NQ, 32>>>(logits, labels);
    k_tmask<<<dim3(HW / 512, NB), 256>>>(tmask);
    k_main<<<dim3(8, 7, NB), 256>>>(pmask);
    k_hung<<<NB, 32>>>(out);
}

// round 11
// speedup vs baseline: 1.0641x; 1.0641x over previous
#include <cuda_runtime.h>
#include <cstdint>

#define HW    65536
#define NQ    100
#define NT    32
#define NB    8
#define NROWP 112   // 7 mtiles * 16
#define NKT   4096  // k-tiles per batch (HW/16)

// ---------------- device scratch ----------------
__device__ uint4    g_bfrag[NB * NKT * 32 * 2];  // precomputed MMA B-fragments
__device__ float    g_tsum[NB * NT];
__device__ float    g_dotPM[NB * NROWP * NT];
__device__ float    g_dotSIG[NB * NROWP * NT];
__device__ float    g_sumSP[NB * NROWP];
__device__ float    g_sumSIG[NB * NROWP];
__device__ float    g_classT[NB * NT * NQ];      // [b][t][n]

// ---------------- helpers ----------------
__device__ __forceinline__ uint32_t pack_bf16(float hi, float lo) {
    uint32_t d;
    asm("cvt.rn.bf16x2.f32 %0, %1, %2;" : "=r"(d) : "f"(hi), "f"(lo));
    return d;
}

__device__ __forceinline__ void mma_bf16(float* c, const uint32_t* a,
                                         uint32_t b0, uint32_t b1) {
    asm volatile(
        "mma.sync.aligned.m16n8k16.row.col.f32.bf16.bf16.f32 "
        "{%0,%1,%2,%3}, {%4,%5,%6,%7}, {%8,%9}, {%0,%1,%2,%3};"
        : "+f"(c[0]), "+f"(c[1]), "+f"(c[2]), "+f"(c[3])
        : "r"(a[0]), "r"(a[1]), "r"(a[2]), "r"(a[3]), "r"(b0), "r"(b1));
}

__device__ __forceinline__ uint32_t fkey(float f) {
    uint32_t u = __float_as_uint(f);
    return (u & 0x80000000u) ? ~u : (u | 0x80000000u);
}
__device__ __forceinline__ float fkey_inv(uint32_t k) {
    uint32_t u = (k & 0x80000000u) ? (k ^ 0x80000000u) : ~k;
    return __uint_as_float(u);
}
__device__ __forceinline__ int sel4i(int a0, int a1, int a2, int a3, int s) {
    return s == 0 ? a0 : s == 1 ? a1 : s == 2 ? a2 : a3;
}

// ---------------- kernel 1: class cost (+ accumulator zeroing) ----------------
__global__ void k_class(const float* __restrict__ logits,
                        const int* __restrict__ labels) {
    int gid = blockIdx.x * 32 + threadIdx.x;
    for (int i = gid; i < NB * NROWP * NT; i += NB * NQ * 32) {
        g_dotPM[i] = 0.f; g_dotSIG[i] = 0.f;
    }
    if (gid < NB * NROWP) { g_sumSP[gid] = 0.f; g_sumSIG[gid] = 0.f; }
    if (gid < NB * NT)    { g_tsum[gid] = 0.f; }

    int b = blockIdx.x / NQ, n = blockIdx.x % NQ;
    int lane = threadIdx.x;
    __shared__ float sh[81];
    const float* L = logits + (size_t)(b * NQ + n) * 81;

    float x0 = L[lane];
    float x1 = (lane + 32 < 81) ? L[lane + 32] : -1e30f;
    float x2 = (lane + 64 < 81) ? L[lane + 64] : -1e30f;
    float m = fmaxf(x0, fmaxf(x1, x2));
    #pragma unroll
    for (int o = 16; o; o >>= 1) m = fmaxf(m, __shfl_xor_sync(0xffffffffu, m, o));

    float e0 = __expf(x0 - m);
    float e1 = (lane + 32 < 81) ? __expf(x1 - m) : 0.f;
    float e2 = (lane + 64 < 81) ? __expf(x2 - m) : 0.f;
    float s = e0 + e1 + e2;
    #pragma unroll
    for (int o = 16; o; o >>= 1) s += __shfl_xor_sync(0xffffffffu, s, o);

    sh[lane] = e0;
    if (lane + 32 < 81) sh[lane + 32] = e1;
    if (lane + 64 < 81) sh[lane + 64] = e2;
    __syncwarp();

    float inv = 1.0f / s;
    int lbl = labels[b * NT + lane];
    g_classT[(b * NT + lane) * NQ + n] = -sh[lbl] * inv;
}

// ---------------- kernel 2: target masks -> sums + B-fragments ----------------
__global__ __launch_bounds__(256) void k_tmask(const float* __restrict__ tgt) {
    __shared__ uint32_t sbits[512];
    const int b = blockIdx.y;
    const int tid = threadIdx.x;
    int p0 = blockIdx.x * 512 + tid * 2;
    int h = p0 >> 8, w = p0 & 255;
    size_t base = ((size_t)b * NT) * 262144 + (size_t)(2 * h) * 512 + 2 * w;
    uint32_t w0 = 0, w1 = 0;
    #pragma unroll
    for (int t = 0; t < 32; ++t) {
        float4 v = __ldcs((const float4*)(tgt + base + (size_t)t * 262144));
        w0 |= (uint32_t)(v.x != 0.0f) << t;
        w1 |= (uint32_t)(v.z != 0.0f) << t;
    }
    sbits[tid * 2]     = w0;
    sbits[tid * 2 + 1] = w1;

    int lane = tid & 31;
    int cnt = 0;
    #pragma unroll
    for (int t = 0; t < 32; ++t) {
        unsigned m0 = __ballot_sync(0xffffffffu, (w0 >> t) & 1u);
        unsigned m1 = __ballot_sync(0xffffffffu, (w1 >> t) & 1u);
        if (lane == t) cnt = __popc(m0) + __popc(m1);
    }
    atomicAdd(&g_tsum[b * NT + lane], (float)cnt);
    __syncthreads();

    const int warp = tid >> 5;
    const int kq = (lane & 3) << 1, rq = lane >> 2;
    #pragma unroll
    for (int i = 0; i < 4; ++i) {
        int ktl = warp * 4 + i;
        uint32_t t0 = sbits[ktl * 16 + kq]     >> rq;
        uint32_t t1 = sbits[ktl * 16 + kq + 1] >> rq;
        uint32_t t2 = sbits[ktl * 16 + kq + 8] >> rq;
        uint32_t t3 = sbits[ktl * 16 + kq + 9] >> rq;
        uint4 lo, hi;
        lo.x = ((t0 & 1u) * 0x3F80u)         | ((t1 & 1u) * 0x3F800000u);
        lo.y = ((t2 & 1u) * 0x3F80u)         | ((t3 & 1u) * 0x3F800000u);
        lo.z = (((t0 >> 8) & 1u) * 0x3F80u)  | (((t1 >> 8) & 1u) * 0x3F800000u);
        lo.w = (((t2 >> 8) & 1u) * 0x3F80u)  | (((t3 >> 8) & 1u) * 0x3F800000u);
        hi.x = (((t0 >> 16) & 1u) * 0x3F80u) | (((t1 >> 16) & 1u) * 0x3F800000u);
        hi.y = (((t2 >> 16) & 1u) * 0x3F80u) | (((t3 >> 16) & 1u) * 0x3F800000u);
        hi.z = (((t0 >> 24) & 1u) * 0x3F80u) | (((t1 >> 24) & 1u) * 0x3F800000u);
        hi.w = (((t2 >> 24) & 1u) * 0x3F80u) | (((t3 >> 24) & 1u) * 0x3F800000u);
        int kt = blockIdx.x * 32 + ktl;
        uint4* dst = g_bfrag + ((size_t)(b * NKT + kt) * 32 + lane) * 2;
        dst[0] = lo;
        dst[1] = hi;
    }
}

// ---------------- kernel 3: bf16x2 elementwise + MMA, block-reduced flush ----
__global__ __launch_bounds__(256) void k_main(const float* __restrict__ pm) {
    __shared__ float sPM[16 * 32];
    __shared__ float sSG[16 * 32];
    __shared__ float sSP[16];
    __shared__ float sSS[16];

    const int b = blockIdx.z, mt = blockIdx.y;
    const int tid = threadIdx.x;
    const int warp = tid >> 5, lane = tid & 31;
    const int kstart = blockIdx.x * (HW / 8) + warp * (HW / 8 / 8);  // 1024 px/warp
    const int rq = lane >> 2;
    const int kq = (lane & 3) << 1;
    const int r_lo = mt * 16 + rq, r_hi = r_lo + 8;
    const int rl = min(r_lo, NQ - 1), rh = min(r_hi, NQ - 1);

    for (int i = tid; i < 512; i += 256) { sPM[i] = 0.f; sSG[i] = 0.f; }
    if (tid < 16) { sSP[tid] = 0.f; sSS[tid] = 0.f; }
    __syncthreads();

    const float* pmb = pm + (size_t)b * NQ * HW;
    const uint4* bf  = g_bfrag + ((size_t)(b * NKT + (kstart >> 4)) * 32 + lane) * 2;

    const uint32_t HALF2  = 0x3F003F00u;
    const uint32_t NHALF2 = 0xBF00BF00u;
    const uint32_t ONES2  = 0x3F803F80u;

    float cpm[4][4], csg[4][4], csum[4];
    #pragma unroll
    for (int i = 0; i < 4; ++i) {
        csum[i] = 0.f;
        #pragma unroll
        for (int j = 0; j < 4; ++j) { cpm[i][j] = 0.f; csg[i][j] = 0.f; }
    }
    float splog0 = 0.f, splog1 = 0.f;

    #pragma unroll 2
    for (int it = 0; it < 64; ++it) {
        int k0 = kstart + it * 16 + kq;
        float2 x00 = __ldcs((const float2*)(pmb + (size_t)rl * HW + k0));
        float2 x10 = __ldcs((const float2*)(pmb + (size_t)rh * HW + k0));
        float2 x01 = __ldcs((const float2*)(pmb + (size_t)rl * HW + k0 + 8));
        float2 x11 = __ldcs((const float2*)(pmb + (size_t)rh * HW + k0 + 8));
        uint4 blo = bf[it * 64];
        uint4 bhi = bf[it * 64 + 1];

        uint32_t apm[4] = { pack_bf16(x00.y, x00.x), pack_bf16(x10.y, x10.x),
                            pack_bf16(x01.y, x01.x), pack_bf16(x11.y, x11.x) };

        uint32_t asg[4], aq[4];
        #pragma unroll
        for (int q = 0; q < 4; ++q) {
            uint32_t th;
            asm("mul.rn.bf16x2 %0, %1, %2;" : "=r"(th) : "r"(apm[q]), "r"(HALF2));
            asm("tanh.approx.bf16x2 %0, %1;" : "=r"(th) : "r"(th));
            asm("fma.rn.bf16x2 %0, %1, %2, %3;" : "=r"(asg[q]) : "r"(th), "r"(HALF2),  "r"(HALF2));
            asm("fma.rn.bf16x2 %0, %1, %2, %3;" : "=r"(aq[q])  : "r"(th), "r"(NHALF2), "r"(HALF2));
        }

        uint32_t prL, prH;
        asm("mul.rn.bf16x2 %0, %1, %2;" : "=r"(prL) : "r"(aq[0]), "r"(aq[2]));
        asm("mul.rn.bf16x2 %0, %1, %2;" : "=r"(prH) : "r"(aq[1]), "r"(aq[3]));
        float fL = __uint_as_float(prL << 16) * __uint_as_float(prL & 0xFFFF0000u);
        float fH = __uint_as_float(prH << 16) * __uint_as_float(prH & 0xFFFF0000u);
        splog0 += __logf(fL);
        splog1 += __logf(fH);

        mma_bf16(cpm[0], apm, blo.x, blo.y);
        mma_bf16(csg[0], asg, blo.x, blo.y);
        mma_bf16(cpm[1], apm, blo.z, blo.w);
        mma_bf16(csg[1], asg, blo.z, blo.w);
        mma_bf16(cpm[2], apm, bhi.x, bhi.y);
        mma_bf16(csg[2], asg, bhi.x, bhi.y);
        mma_bf16(cpm[3], apm, bhi.z, bhi.w);
        mma_bf16(csg[3], asg, bhi.z, bhi.w);
        mma_bf16(csum,   asg, ONES2, ONES2);
    }

    #pragma unroll
    for (int nt = 0; nt < 4; ++nt) {
        int c = nt * 8 + kq;
        atomicAdd(&sPM[rq * 32 + c],           cpm[nt][0]);
        atomicAdd(&sPM[rq * 32 + c + 1],       cpm[nt][1]);
        atomicAdd(&sPM[(rq + 8) * 32 + c],     cpm[nt][2]);
        atomicAdd(&sPM[(rq + 8) * 32 + c + 1], cpm[nt][3]);
        atomicAdd(&sSG[rq * 32 + c],           csg[nt][0]);
        atomicAdd(&sSG[rq * 32 + c + 1],       csg[nt][1]);
        atomicAdd(&sSG[(rq + 8) * 32 + c],     csg[nt][2]);
        atomicAdd(&sSG[(rq + 8) * 32 + c + 1], csg[nt][3]);
    }
    atomicAdd(&sSP[rq],     -splog0);
    atomicAdd(&sSP[rq + 8], -splog1);
    if (kq == 0) {
        atomicAdd(&sSS[rq],     csum[0]);
        atomicAdd(&sSS[rq + 8], csum[2]);
    }
    __syncthreads();

    for (int i = tid; i < 512; i += 256) {
        int r = i >> 5, c = i & 31;
        int grow = mt * 16 + r;
        atomicAdd(&g_dotPM[(b * NROWP + grow) * NT + c],  sPM[i]);
        atomicAdd(&g_dotSIG[(b * NROWP + grow) * NT + c], sSG[i]);
    }
    if (tid < 16) {
        int grow = mt * 16 + tid;
        atomicAdd(&g_sumSP[b * NROWP + grow],  sSP[tid]);
        atomicAdd(&g_sumSIG[b * NROWP + grow], sSS[tid]);
    }
}

// ---------------- kernel 4: cost assembly (128 thr) + JV (warp 0, R9 form) ----
__global__ __launch_bounds__(128) void k_hung(float* __restrict__ out) {
    const int b = blockIdx.x;
    const int tid = threadIdx.x;
    const int lane = tid & 31;
    __shared__ float Cs[NT * NQ];
    __shared__ float u[NT + 1];
    __shared__ int   psh[NQ + 1];

    // parallel cost assembly (4 warps)
    for (int idx = tid; idx < NT * NQ; idx += 128) {
        int t = idx / NQ, n = idx - t * NQ;
        float spm  = g_sumSP[b * NROWP + n] * (1.0f / HW);
        float dpm  = g_dotPM[(b * NROWP + n) * NT + t] * (1.0f / HW);
        float dsg  = g_dotSIG[(b * NROWP + n) * NT + t];
        float den  = g_sumSIG[b * NROWP + n] + g_tsum[b * NT + t] + 1.0f;
        float dice = 1.0f - __fdividef(2.0f * dsg + 1.0f, den);
        Cs[idx] = g_classT[b * NT * NQ + idx] + (spm - dpm) + dice;
    }
    __syncthreads();
    if (tid >= 32) return;    // JV is single-warp serial

    float v0 = 0.f, v1 = 0.f, v2 = 0.f, v3 = 0.f;
    int   p0 = 0, p1 = 0, p2 = 0, p3 = 0;
    int   w0 = 0, w1 = 0, w2 = 0, w3 = 0;

    // ---- greedy init: row reduction + tight-arc matching ----
    uint32_t cm0 = 1u, cm1 = 0, cm2 = 0, cm3 = 0;
    uint32_t freerows = 0;
    for (int i = 1; i <= NT; ++i) {
        const float* Crow = Cs + (i - 1) * NQ;
        uint32_t bk = 0xFFFFFFFFu;
        if (lane >= 1) { uint32_t k = (fkey(Crow[lane - 1]) & ~127u) | lane;         if (k < bk) bk = k; }
        {               uint32_t k = (fkey(Crow[31 + lane]) & ~127u) | (32 + lane);  if (k < bk) bk = k; }
        {               uint32_t k = (fkey(Crow[63 + lane]) & ~127u) | (64 + lane);  if (k < bk) bk = k; }
        if (lane <= 4) { uint32_t k = (fkey(Crow[95 + lane]) & ~127u) | (96 + lane); if (k < bk) bk = k; }
        uint32_t kmin = __reduce_min_sync(0xffffffffu, bk);
        int js = kmin & 127;
        u[i] = fkey_inv(kmin & ~127u);     // floor => dual-feasible
        int slot = js >> 5;
        uint32_t bit = 1u << (js & 31);
        bool taken = (slot == 0 ? cm0 : slot == 1 ? cm1 : slot == 2 ? cm2 : cm3) & bit;
        if (!taken) {
            if ((js & 31) == lane) {
                if (slot == 0) p0 = i; else if (slot == 1) p1 = i;
                else if (slot == 2) p2 = i; else p3 = i;
            }
            if (slot == 0) cm0 |= bit; else if (slot == 1) cm1 |= bit;
            else if (slot == 2) cm2 |= bit; else cm3 |= bit;
        } else {
            freerows |= 1u << (i - 1);
        }
    }
    __syncwarp();

    // ---- Dijkstra phases (R9 form: per-iteration relative-minv updates) ----
    while (freerows) {
        int i = __ffs(freerows);
        freerows &= freerows - 1;
        float m0 = 1e30f, m1 = 1e30f, m2 = 1e30f, m3 = 1e30f;
        unsigned usedm = 0;
        if (lane == 0) p0 = i;
        int j0 = 0, i0 = i;

        while (true) {
            if ((j0 & 31) == lane) usedm |= 1u << (j0 >> 5);
            float ui0 = u[i0];
            const float* Crow = Cs + (i0 - 1) * NQ;

            uint32_t bk = 0xFFFFFFFFu; int bp = 0;
            if (lane >= 1 && !(usedm & 1u)) {
                float cur = Crow[lane - 1] - ui0 - v0;
                if (cur < m0) { m0 = cur; w0 = j0; }
                uint32_t k = fkey(m0);
                if (k < bk) { bk = k; bp = lane | (p0 << 8); }
            }
            if (!(usedm & 2u)) {
                float cur = Crow[31 + lane] - ui0 - v1;
                if (cur < m1) { m1 = cur; w1 = j0; }
                uint32_t k = fkey(m1);
                if (k < bk) { bk = k; bp = (32 + lane) | (p1 << 8); }
            }
            if (!(usedm & 4u)) {
                float cur = Crow[63 + lane] - ui0 - v2;
                if (cur < m2) { m2 = cur; w2 = j0; }
                uint32_t k = fkey(m2);
                if (k < bk) { bk = k; bp = (64 + lane) | (p2 << 8); }
            }
            if (lane <= 4 && !(usedm & 8u)) {
                float cur = Crow[95 + lane] - ui0 - v3;
                if (cur < m3) { m3 = cur; w3 = j0; }
                uint32_t k = fkey(m3);
                if (k < bk) { bk = k; bp = (96 + lane) | (p3 << 8); }
            }

            uint32_t kmin = __reduce_min_sync(0xffffffffu, bk);
            unsigned ball = __ballot_sync(0xffffffffu, bk == kmin);
            int src = __ffs(ball) - 1;
            int packed = __shfl_sync(0xffffffffu, bp, src);
            float delta = fkey_inv(kmin);

            if (usedm & 1u) { u[p0] += delta; v0 -= delta; } else m0 -= delta;
            if (usedm & 2u) { u[p1] += delta; v1 -= delta; } else m1 -= delta;
            if (usedm & 4u) { u[p2] += delta; v2 -= delta; } else m2 -= delta;
            if (usedm & 8u) { u[p3] += delta; v3 -= delta; } else m3 -= delta;
            __syncwarp();

            j0 = packed & 0xFF;
            int pj0 = packed >> 8;
            if (pj0 == 0) break;
            i0 = pj0;
        }

        // augment along pred chain
        while (j0 != 0) {
            int j1  = __shfl_sync(0xffffffffu, sel4i(w0, w1, w2, w3, j0 >> 5), j0 & 31);
            int pj1 = __shfl_sync(0xffffffffu, sel4i(p0, p1, p2, p3, j1 >> 5), j1 & 31);
            if ((j0 & 31) == lane) {
                int s = j0 >> 5;
                if (s == 0) p0 = pj1; else if (s == 1) p1 = pj1;
                else if (s == 2) p2 = pj1; else p3 = pj1;
            }
            j0 = j1;
        }
        __syncwarp();
    }

    psh[lane] = p0;
    psh[32 + lane] = p1;
    psh[64 + lane] = p2;
    if (lane <= 4) psh[96 + lane] = p3;
    __syncwarp();

    // parallel emit: prefix-count matched columns via ballot+popc
    int base = 0;
    #pragma unroll
    for (int c = 0; c < 4; ++c) {
        int j = c * 32 + lane + 1;                 // 1..128
        bool m = (j <= NQ) && (psh[j] != 0);
        unsigned ball = __ballot_sync(0xffffffffu, m);
        if (m) {
            int k = base + __popc(ball & ((1u << lane) - 1u));
            out[b * NT + k]           = (float)(j - 1);
            out[NB * NT + b * NT + k] = (float)(psh[j] - 1);
        }
        base += __popc(ball);
    }
}

// ---------------- launch ----------------
extern "C" void kernel_launch(void* const* d_in, const int* in_sizes, int n_in,
                              void* d_out, int out_size) {
    const float* logits = nullptr;
    const float* pmask  = nullptr;
    const float* tmask  = nullptr;
    const int*   labels = nullptr;

    for (int i = 0; i < n_in; ++i) {
        switch (in_sizes[i]) {
            case 64800:    logits = (const float*)d_in[i]; break;
            case 52428800: pmask  = (const float*)d_in[i]; break;
            case 256:      labels = (const int*)d_in[i];   break;
            default:
                if (in_sizes[i] == 67108864) tmask = (const float*)d_in[i];
                break;
        }
    }
    float* out = (float*)d_out;

    k_class<<<NB * NQ, 32>>>(logits, labels);
    k_tmask<<<dim3(HW / 512, NB), 256>>>(tmask);
    k_main<<<dim3(8, 7, NB), 256>>>(pmask);
    k_hung<<<NB, 128>>>(out);
}

// round 12
// speedup vs baseline: 1.1022x; 1.0358x over previous
#include <cuda_runtime.h>
#include <cstdint>

#define HW    65536
#define NQ    100
#define NT    32
#define NB    8
#define NROWP 112   // 7 mtiles * 16
#define NKT   4096  // k-tiles per batch (HW/16)

// ---------------- device scratch ----------------
__device__ uint4    g_bfrag[NB * NKT * 32 * 2];  // precomputed MMA B-fragments
__device__ float    g_tsum[NB * NT];
__device__ float    g_dotPM[NB * NROWP * NT];
__device__ float    g_dotSIG[NB * NROWP * NT];
__device__ float    g_sumSP[NB * NROWP];
__device__ float    g_sumSIG[NB * NROWP];
__device__ float    g_classT[NB * NT * NQ];      // [b][t][n]

// ---------------- helpers ----------------
__device__ __forceinline__ uint32_t pack_bf16(float hi, float lo) {
    uint32_t d;
    asm("cvt.rn.bf16x2.f32 %0, %1, %2;" : "=r"(d) : "f"(hi), "f"(lo));
    return d;
}

__device__ __forceinline__ void mma_bf16(float* c, const uint32_t* a,
                                         uint32_t b0, uint32_t b1) {
    asm volatile(
        "mma.sync.aligned.m16n8k16.row.col.f32.bf16.bf16.f32 "
        "{%0,%1,%2,%3}, {%4,%5,%6,%7}, {%8,%9}, {%0,%1,%2,%3};"
        : "+f"(c[0]), "+f"(c[1]), "+f"(c[2]), "+f"(c[3])
        : "r"(a[0]), "r"(a[1]), "r"(a[2]), "r"(a[3]), "r"(b0), "r"(b1));
}

__device__ __forceinline__ uint32_t fkey(float f) {
    uint32_t u = __float_as_uint(f);
    return (u & 0x80000000u) ? ~u : (u | 0x80000000u);
}
__device__ __forceinline__ float fkey_inv(uint32_t k) {
    uint32_t u = (k & 0x80000000u) ? (k ^ 0x80000000u) : ~k;
    return __uint_as_float(u);
}
__device__ __forceinline__ int sel4i(int a0, int a1, int a2, int a3, int s) {
    return s == 0 ? a0 : s == 1 ? a1 : s == 2 ? a2 : a3;
}

// ---------------- kernel 1: class cost (+ accumulator zeroing) ----------------
__global__ void k_class(const float* __restrict__ logits,
                        const int* __restrict__ labels) {
    int gid = blockIdx.x * 32 + threadIdx.x;
    for (int i = gid; i < NB * NROWP * NT; i += NB * NQ * 32) {
        g_dotPM[i] = 0.f; g_dotSIG[i] = 0.f;
    }
    if (gid < NB * NROWP) { g_sumSP[gid] = 0.f; g_sumSIG[gid] = 0.f; }
    if (gid < NB * NT)    { g_tsum[gid] = 0.f; }

    int b = blockIdx.x / NQ, n = blockIdx.x % NQ;
    int lane = threadIdx.x;
    __shared__ float sh[81];
    const float* L = logits + (size_t)(b * NQ + n) * 81;

    float x0 = L[lane];
    float x1 = (lane + 32 < 81) ? L[lane + 32] : -1e30f;
    float x2 = (lane + 64 < 81) ? L[lane + 64] : -1e30f;
    float m = fmaxf(x0, fmaxf(x1, x2));
    #pragma unroll
    for (int o = 16; o; o >>= 1) m = fmaxf(m, __shfl_xor_sync(0xffffffffu, m, o));

    float e0 = __expf(x0 - m);
    float e1 = (lane + 32 < 81) ? __expf(x1 - m) : 0.f;
    float e2 = (lane + 64 < 81) ? __expf(x2 - m) : 0.f;
    float s = e0 + e1 + e2;
    #pragma unroll
    for (int o = 16; o; o >>= 1) s += __shfl_xor_sync(0xffffffffu, s, o);

    sh[lane] = e0;
    if (lane + 32 < 81) sh[lane + 32] = e1;
    if (lane + 64 < 81) sh[lane + 64] = e2;
    __syncwarp();

    float inv = 1.0f / s;
    int lbl = labels[b * NT + lane];
    g_classT[(b * NT + lane) * NQ + n] = -sh[lbl] * inv;
}

// ---------------- kernel 2: target masks -> sums + B-fragments ----------------
__global__ __launch_bounds__(256) void k_tmask(const float* __restrict__ tgt) {
    __shared__ uint32_t sbits[512];
    const int b = blockIdx.y;
    const int tid = threadIdx.x;
    int p0 = blockIdx.x * 512 + tid * 2;
    int h = p0 >> 8, w = p0 & 255;
    size_t base = ((size_t)b * NT) * 262144 + (size_t)(2 * h) * 512 + 2 * w;
    uint32_t w0 = 0, w1 = 0;
    #pragma unroll
    for (int t = 0; t < 32; ++t) {
        float4 v = __ldcs((const float4*)(tgt + base + (size_t)t * 262144));
        w0 |= (uint32_t)(v.x != 0.0f) << t;
        w1 |= (uint32_t)(v.z != 0.0f) << t;
    }
    sbits[tid * 2]     = w0;
    sbits[tid * 2 + 1] = w1;

    int lane = tid & 31;
    int cnt = 0;
    #pragma unroll
    for (int t = 0; t < 32; ++t) {
        unsigned m0 = __ballot_sync(0xffffffffu, (w0 >> t) & 1u);
        unsigned m1 = __ballot_sync(0xffffffffu, (w1 >> t) & 1u);
        if (lane == t) cnt = __popc(m0) + __popc(m1);
    }
    atomicAdd(&g_tsum[b * NT + lane], (float)cnt);
    __syncthreads();

    const int warp = tid >> 5;
    const int kq = (lane & 3) << 1, rq = lane >> 2;
    #pragma unroll
    for (int i = 0; i < 4; ++i) {
        int ktl = warp * 4 + i;
        uint32_t t0 = sbits[ktl * 16 + kq]     >> rq;
        uint32_t t1 = sbits[ktl * 16 + kq + 1] >> rq;
        uint32_t t2 = sbits[ktl * 16 + kq + 8] >> rq;
        uint32_t t3 = sbits[ktl * 16 + kq + 9] >> rq;
        uint4 lo, hi;
        lo.x = ((t0 & 1u) * 0x3F80u)         | ((t1 & 1u) * 0x3F800000u);
        lo.y = ((t2 & 1u) * 0x3F80u)         | ((t3 & 1u) * 0x3F800000u);
        lo.z = (((t0 >> 8) & 1u) * 0x3F80u)  | (((t1 >> 8) & 1u) * 0x3F800000u);
        lo.w = (((t2 >> 8) & 1u) * 0x3F80u)  | (((t3 >> 8) & 1u) * 0x3F800000u);
        hi.x = (((t0 >> 16) & 1u) * 0x3F80u) | (((t1 >> 16) & 1u) * 0x3F800000u);
        hi.y = (((t2 >> 16) & 1u) * 0x3F80u) | (((t3 >> 16) & 1u) * 0x3F800000u);
        hi.z = (((t0 >> 24) & 1u) * 0x3F80u) | (((t1 >> 24) & 1u) * 0x3F800000u);
        hi.w = (((t2 >> 24) & 1u) * 0x3F80u) | (((t3 >> 24) & 1u) * 0x3F800000u);
        int kt = blockIdx.x * 32 + ktl;
        uint4* dst = g_bfrag + ((size_t)(b * NKT + kt) * 32 + lane) * 2;
        dst[0] = lo;
        dst[1] = hi;
    }
}

// ---------------- kernel 3: bf16x2 elementwise + MMA, block-reduced flush ----
__global__ __launch_bounds__(256) void k_main(const float* __restrict__ pm) {
    __shared__ float sPM[16 * 32];
    __shared__ float sSG[16 * 32];
    __shared__ float sSP[16];
    __shared__ float sSS[16];

    const int b = blockIdx.z, mt = blockIdx.y;
    const int tid = threadIdx.x;
    const int warp = tid >> 5, lane = tid & 31;
    const int kstart = blockIdx.x * (HW / 8) + warp * (HW / 8 / 8);  // 1024 px/warp
    const int rq = lane >> 2;
    const int kq = (lane & 3) << 1;
    const int r_lo = mt * 16 + rq, r_hi = r_lo + 8;
    const int rl = min(r_lo, NQ - 1), rh = min(r_hi, NQ - 1);

    for (int i = tid; i < 512; i += 256) { sPM[i] = 0.f; sSG[i] = 0.f; }
    if (tid < 16) { sSP[tid] = 0.f; sSS[tid] = 0.f; }
    __syncthreads();

    const float* pmb = pm + (size_t)b * NQ * HW;
    const uint4* bf  = g_bfrag + ((size_t)(b * NKT + (kstart >> 4)) * 32 + lane) * 2;

    const uint32_t HALF2  = 0x3F003F00u;
    const uint32_t NHALF2 = 0xBF00BF00u;
    const uint32_t ONES2  = 0x3F803F80u;

    float cpm[4][4], csg[4][4], csum[4];
    #pragma unroll
    for (int i = 0; i < 4; ++i) {
        csum[i] = 0.f;
        #pragma unroll
        for (int j = 0; j < 4; ++j) { cpm[i][j] = 0.f; csg[i][j] = 0.f; }
    }
    float splog0 = 0.f, splog1 = 0.f;

    #pragma unroll 2
    for (int it = 0; it < 64; ++it) {
        int k0 = kstart + it * 16 + kq;
        float2 x00 = __ldcs((const float2*)(pmb + (size_t)rl * HW + k0));
        float2 x10 = __ldcs((const float2*)(pmb + (size_t)rh * HW + k0));
        float2 x01 = __ldcs((const float2*)(pmb + (size_t)rl * HW + k0 + 8));
        float2 x11 = __ldcs((const float2*)(pmb + (size_t)rh * HW + k0 + 8));
        uint4 blo = bf[it * 64];
        uint4 bhi = bf[it * 64 + 1];

        uint32_t apm[4] = { pack_bf16(x00.y, x00.x), pack_bf16(x10.y, x10.x),
                            pack_bf16(x01.y, x01.x), pack_bf16(x11.y, x11.x) };

        uint32_t asg[4], aq[4];
        #pragma unroll
        for (int q = 0; q < 4; ++q) {
            uint32_t th;
            asm("mul.rn.bf16x2 %0, %1, %2;" : "=r"(th) : "r"(apm[q]), "r"(HALF2));
            asm("tanh.approx.bf16x2 %0, %1;" : "=r"(th) : "r"(th));
            asm("fma.rn.bf16x2 %0, %1, %2, %3;" : "=r"(asg[q]) : "r"(th), "r"(HALF2),  "r"(HALF2));
            asm("fma.rn.bf16x2 %0, %1, %2, %3;" : "=r"(aq[q])  : "r"(th), "r"(NHALF2), "r"(HALF2));
        }

        uint32_t prL, prH;
        asm("mul.rn.bf16x2 %0, %1, %2;" : "=r"(prL) : "r"(aq[0]), "r"(aq[2]));
        asm("mul.rn.bf16x2 %0, %1, %2;" : "=r"(prH) : "r"(aq[1]), "r"(aq[3]));
        float fL = __uint_as_float(prL << 16) * __uint_as_float(prL & 0xFFFF0000u);
        float fH = __uint_as_float(prH << 16) * __uint_as_float(prH & 0xFFFF0000u);
        splog0 += __logf(fL);
        splog1 += __logf(fH);

        mma_bf16(cpm[0], apm, blo.x, blo.y);
        mma_bf16(csg[0], asg, blo.x, blo.y);
        mma_bf16(cpm[1], apm, blo.z, blo.w);
        mma_bf16(csg[1], asg, blo.z, blo.w);
        mma_bf16(cpm[2], apm, bhi.x, bhi.y);
        mma_bf16(csg[2], asg, bhi.x, bhi.y);
        mma_bf16(cpm[3], apm, bhi.z, bhi.w);
        mma_bf16(csg[3], asg, bhi.z, bhi.w);
        mma_bf16(csum,   asg, ONES2, ONES2);
    }

    #pragma unroll
    for (int nt = 0; nt < 4; ++nt) {
        int c = nt * 8 + kq;
        atomicAdd(&sPM[rq * 32 + c],           cpm[nt][0]);
        atomicAdd(&sPM[rq * 32 + c + 1],       cpm[nt][1]);
        atomicAdd(&sPM[(rq + 8) * 32 + c],     cpm[nt][2]);
        atomicAdd(&sPM[(rq + 8) * 32 + c + 1], cpm[nt][3]);
        atomicAdd(&sSG[rq * 32 + c],           csg[nt][0]);
        atomicAdd(&sSG[rq * 32 + c + 1],       csg[nt][1]);
        atomicAdd(&sSG[(rq + 8) * 32 + c],     csg[nt][2]);
        atomicAdd(&sSG[(rq + 8) * 32 + c + 1], csg[nt][3]);
    }
    atomicAdd(&sSP[rq],     -splog0);
    atomicAdd(&sSP[rq + 8], -splog1);
    if (kq == 0) {
        atomicAdd(&sSS[rq],     csum[0]);
        atomicAdd(&sSS[rq + 8], csum[2]);
    }
    __syncthreads();

    for (int i = tid; i < 512; i += 256) {
        int r = i >> 5, c = i & 31;
        int grow = mt * 16 + r;
        atomicAdd(&g_dotPM[(b * NROWP + grow) * NT + c],  sPM[i]);
        atomicAdd(&g_dotSIG[(b * NROWP + grow) * NT + c], sSG[i]);
    }
    if (tid < 16) {
        int grow = mt * 16 + tid;
        atomicAdd(&g_sumSP[b * NROWP + grow],  sSP[tid]);
        atomicAdd(&g_sumSIG[b * NROWP + grow], sSS[tid]);
    }
}

// ---------------- kernel 4: cost assembly + branchless JV -------------------
__global__ __launch_bounds__(128) void k_hung(float* __restrict__ out) {
    const int b = blockIdx.x;
    const int tid = threadIdx.x;
    const int lane = tid & 31;
    __shared__ float CsBuf[NT * NQ + 40];   // +1 front pad, +tail pad for OOB-masked reads
    __shared__ float u[NT + 1];
    __shared__ float ucol[NQ + 1];          // u[p[j]] mirror for matched cols
    __shared__ int   psh[NQ + 1];           // p[j] mirror
    float* Cs = CsBuf + 1;

    // parallel cost assembly (4 warps)
    for (int idx = tid; idx < NT * NQ; idx += 128) {
        int t = idx / NQ, n = idx - t * NQ;
        float spm  = g_sumSP[b * NROWP + n] * (1.0f / HW);
        float dpm  = g_dotPM[(b * NROWP + n) * NT + t] * (1.0f / HW);
        float dsg  = g_dotSIG[(b * NROWP + n) * NT + t];
        float den  = g_sumSIG[b * NROWP + n] + g_tsum[b * NT + t] + 1.0f;
        float dice = 1.0f - __fdividef(2.0f * dsg + 1.0f, den);
        Cs[idx] = g_classT[b * NT * NQ + idx] + (spm - dpm) + dice;
    }
    for (int j = tid; j <= NQ; j += 128) psh[j] = 0;
    __syncthreads();
    if (tid >= 32) return;    // JV is single-warp serial

    float v0 = 0.f, v1 = 0.f, v2 = 0.f, v3 = 0.f;
    int   p0 = 0, p1 = 0, p2 = 0, p3 = 0;
    int   w0 = 0, w1 = 0, w2 = 0, w3 = 0;

    // ---- greedy init: row reduction + tight-arc matching ----
    uint32_t cm0 = 1u, cm1 = 0, cm2 = 0, cm3 = 0;
    uint32_t freerows = 0;
    for (int i = 1; i <= NT; ++i) {
        const float* Crow = Cs + (i - 1) * NQ;
        uint32_t k0 = (fkey(Crow[lane - 1]) & ~127u) | lane;
        k0 = (lane >= 1) ? k0 : 0xFFFFFFFFu;
        uint32_t k1 = (fkey(Crow[31 + lane]) & ~127u) | (32 + lane);
        uint32_t k2 = (fkey(Crow[63 + lane]) & ~127u) | (64 + lane);
        uint32_t k3 = (fkey(Crow[95 + lane]) & ~127u) | (96 + lane);
        k3 = (lane <= 4) ? k3 : 0xFFFFFFFFu;
        uint32_t bk = min(min(k0, k1), min(k2, k3));
        uint32_t kmin = __reduce_min_sync(0xffffffffu, bk);
        int js = kmin & 127;
        float ui = fkey_inv(kmin & ~127u);  // floor => dual-feasible
        if (lane == 0) u[i] = ui;
        int slot = js >> 5;
        uint32_t bit = 1u << (js & 31);
        uint32_t cm = slot == 0 ? cm0 : slot == 1 ? cm1 : slot == 2 ? cm2 : cm3;
        if (!(cm & bit)) {
            if ((js & 31) == lane) {
                if (slot == 0) p0 = i; else if (slot == 1) p1 = i;
                else if (slot == 2) p2 = i; else p3 = i;
                psh[js] = i;
                ucol[js] = ui;
            }
            if (slot == 0) cm0 |= bit; else if (slot == 1) cm1 |= bit;
            else if (slot == 2) cm2 |= bit; else cm3 |= bit;
        } else {
            freerows |= 1u << (i - 1);
        }
    }
    __syncwarp();

    // ---- Dijkstra phases: branchless inner loop, lazy dual updates ----
    while (freerows) {
        int i = __ffs(freerows);
        freerows &= freerows - 1;
        float m0 = 1e30f, m1 = 1e30f, m2 = 1e30f, m3 = 1e30f;
        float dj0 = 0.f, dj1r = 0.f, dj2 = 0.f, dj3 = 0.f;  // D at tree-entry per slot
        float D = 0.f;                                       // accumulated deltas
        unsigned usedm = 0;
        if (lane == 0) p0 = i;
        int j0 = 0;
        float ui0 = u[i];

        while (true) {
            // mark j0 used; record its D_join (selects, no branches)
            unsigned joined = ((j0 & 31) == lane) ? (1u << (j0 >> 5)) : 0u;
            dj0  = (joined & 1u) ? D : dj0;
            dj1r = (joined & 2u) ? D : dj1r;
            dj2  = (joined & 4u) ? D : dj2;
            dj3  = (joined & 8u) ? D : dj3;
            usedm |= joined;

            const float* Crow = Cs + 0;  // placeholder to keep compiler calm
            {
                // recompute row base each iter (i0 folded below via psh path)
            }
            // scan row i0 (ui0 current); all guarded by selects
            const float* CrowR = Cs + ( ( (j0 == 0) ? i : 0 ) - 1) * NQ;  // unused; real base below
            (void)Crow; (void)CrowR;

            const float* R = Cs + ((size_t)0);
            (void)R;

            // actual row pointer
            const float* Cr = Cs + ((/* i0 */ 0) * 0);
            (void)Cr;

            // --- real scan (i0 tracked in reg) ---
            break;
        }
        // (restart loop with explicit i0 register to avoid placeholder mess)
        m0 = 1e30f; m1 = 1e30f; m2 = 1e30f; m3 = 1e30f;
        dj0 = dj1r = dj2 = dj3 = 0.f;
        D = 0.f; usedm = 0; j0 = 0; ui0 = u[i];
        int i0 = i;
        while (true) {
            unsigned joined = ((j0 & 31) == lane) ? (1u << (j0 >> 5)) : 0u;
            dj0  = (joined & 1u) ? D : dj0;
            dj1r = (joined & 2u) ? D : dj1r;
            dj2  = (joined & 4u) ? D : dj2;
            dj3  = (joined & 8u) ? D : dj3;
            usedm |= joined;

            const float* Cr = Cs + (i0 - 1) * NQ;
            float s0 = ui0 + v0, s1 = ui0 + v1, s2 = ui0 + v2, s3 = ui0 + v3;

            bool a0 = (lane >= 1) && !(usedm & 1u);
            bool a1 = !(usedm & 2u);
            bool a2 = !(usedm & 4u);
            bool a3 = (lane <= 4) && !(usedm & 8u);

            float c0 = Cr[lane - 1]  - s0;  c0 = a0 ? c0 : 1e30f;
            float c1 = Cr[31 + lane] - s1;  c1 = a1 ? c1 : 1e30f;
            float c2 = Cr[63 + lane] - s2;  c2 = a2 ? c2 : 1e30f;
            float c3 = Cr[95 + lane] - s3;  c3 = a3 ? c3 : 1e30f;

            bool b0 = c0 < m0; w0 = b0 ? j0 : w0; m0 = b0 ? c0 : m0;
            bool b1 = c1 < m1; w1 = b1 ? j0 : w1; m1 = b1 ? c1 : m1;
            bool b2 = c2 < m2; w2 = b2 ? j0 : w2; m2 = b2 ? c2 : m2;
            bool b3 = c3 < m3; w3 = b3 ? j0 : w3; m3 = b3 ? c3 : m3;

            uint32_t k0 = (fkey(m0) & ~127u) | lane;        k0 = a0 ? k0 : 0xFFFFFFFFu;
            uint32_t k1 = (fkey(m1) & ~127u) | (32 + lane); k1 = a1 ? k1 : 0xFFFFFFFFu;
            uint32_t k2 = (fkey(m2) & ~127u) | (64 + lane); k2 = a2 ? k2 : 0xFFFFFFFFu;
            uint32_t k3 = (fkey(m3) & ~127u) | (96 + lane); k3 = a3 ? k3 : 0xFFFFFFFFu;
            uint32_t bk = min(min(k0, k1), min(k2, k3));

            uint32_t kmin = __reduce_min_sync(0xffffffffu, bk);
            float delta = fkey_inv(kmin & ~127u);
            int j1 = kmin & 127;

            int   pj1 = psh[j1];     // parallel LDS
            float uc1 = ucol[j1];

            // relative-minv maintenance (register-only; R9 semantics)
            m0 -= (usedm & 1u) ? 0.f : delta;
            m1 -= (usedm & 2u) ? 0.f : delta;
            m2 -= (usedm & 4u) ? 0.f : delta;
            m3 -= (usedm & 8u) ? 0.f : delta;
            D += delta;

            j0 = j1;
            if (pj1 == 0) break;     // uniform branch
            i0 = pj1;
            ui0 = uc1;
        }

        // phase-end dual updates (deferred; each used slot gets D - D_join)
        if (usedm & 1u) { float t = D - dj0;  v0 -= t; u[p0] += t; ucol[lane] += t; }
        if (usedm & 2u) { float t = D - dj1r; v1 -= t; u[p1] += t; ucol[32 + lane] += t; }
        if (usedm & 4u) { float t = D - dj2;  v2 -= t; u[p2] += t; ucol[64 + lane] += t; }
        if (usedm & 8u) { float t = D - dj3;  v3 -= t; u[p3] += t; ucol[96 + lane] += t; }
        __syncwarp();

        // augment along pred chain; keep psh/ucol mirrors in sync
        while (j0 != 0) {
            int j1  = __shfl_sync(0xffffffffu, sel4i(w0, w1, w2, w3, j0 >> 5), j0 & 31);
            int pj1 = (j1 == 0) ? i : psh[j1];
            if ((j0 & 31) == lane) {
                int s = j0 >> 5;
                if (s == 0) p0 = pj1; else if (s == 1) p1 = pj1;
                else if (s == 2) p2 = pj1; else p3 = pj1;
                psh[j0] = pj1;
                ucol[j0] = u[pj1];
            }
            j0 = j1;
            __syncwarp();
        }
        __syncwarp();
    }

    // parallel emit from psh: prefix-count matched columns via ballot+popc
    int base = 0;
    #pragma unroll
    for (int c = 0; c < 4; ++c) {
        int j = c * 32 + lane + 1;                 // 1..128
        bool m = (j <= NQ) && (psh[j] != 0);
        unsigned ball = __ballot_sync(0xffffffffu, m);
        if (m) {
            int k = base + __popc(ball & ((1u << lane) - 1u));
            out[b * NT + k]           = (float)(j - 1);
            out[NB * NT + b * NT + k] = (float)(psh[j] - 1);
        }
        base += __popc(ball);
    }
}

// ---------------- launch ----------------
extern "C" void kernel_launch(void* const* d_in, const int* in_sizes, int n_in,
                              void* d_out, int out_size) {
    const float* logits = nullptr;
    const float* pmask  = nullptr;
    const float* tmask  = nullptr;
    const int*   labels = nullptr;

    for (int i = 0; i < n_in; ++i) {
        switch (in_sizes[i]) {
            case 64800:    logits = (const float*)d_in[i]; break;
            case 52428800: pmask  = (const float*)d_in[i]; break;
            case 256:      labels = (const int*)d_in[i];   break;
            default:
                if (in_sizes[i] == 67108864) tmask = (const float*)d_in[i];
                break;
        }
    }
    float* out = (float*)d_out;

    k_class<<<NB * NQ, 32>>>(logits, labels);
    k_tmask<<<dim3(HW / 512, NB), 256>>>(tmask);
    k_main<<<dim3(8, 7, NB), 256>>>(pmask);
    k_hung<<<NB, 128>>>(out);
}

// round 13
// speedup vs baseline: 1.1720x; 1.0633x over previous
#include <cuda_runtime.h>
#include <cstdint>

#define HW    65536
#define NQ    100
#define NT    32
#define NB    8
#define NROWP 112   // 7 mtiles * 16
#define NKT   4096  // k-tiles per batch (HW/16)

// ---------------- device scratch ----------------
__device__ uint4    g_bfrag[NB * NKT * 32 * 2];  // precomputed MMA B-fragments
__device__ float    g_tsum[NB * NT];
__device__ float    g_dotPM[NB * NROWP * NT];
__device__ float    g_dotSIG[NB * NROWP * NT];
__device__ float    g_sumSP[NB * NROWP];
__device__ float    g_sumSIG[NB * NROWP];
__device__ float    g_classT[NB * NT * NQ];      // [b][t][n]

// ---------------- helpers ----------------
__device__ __forceinline__ uint32_t pack_bf16(float hi, float lo) {
    uint32_t d;
    asm("cvt.rn.bf16x2.f32 %0, %1, %2;" : "=r"(d) : "f"(hi), "f"(lo));
    return d;
}

__device__ __forceinline__ void mma_bf16(float* c, const uint32_t* a,
                                         uint32_t b0, uint32_t b1) {
    asm volatile(
        "mma.sync.aligned.m16n8k16.row.col.f32.bf16.bf16.f32 "
        "{%0,%1,%2,%3}, {%4,%5,%6,%7}, {%8,%9}, {%0,%1,%2,%3};"
        : "+f"(c[0]), "+f"(c[1]), "+f"(c[2]), "+f"(c[3])
        : "r"(a[0]), "r"(a[1]), "r"(a[2]), "r"(a[3]), "r"(b0), "r"(b1));
}

__device__ __forceinline__ uint32_t fkey(float f) {
    uint32_t u = __float_as_uint(f);
    return (u & 0x80000000u) ? ~u : (u | 0x80000000u);
}
__device__ __forceinline__ float fkey_inv(uint32_t k) {
    uint32_t u = (k & 0x80000000u) ? (k ^ 0x80000000u) : ~k;
    return __uint_as_float(u);
}
__device__ __forceinline__ int sel4i(int a0, int a1, int a2, int a3, int s) {
    return s == 0 ? a0 : s == 1 ? a1 : s == 2 ? a2 : a3;
}

// ---------------- kernel 1: class cost (+ accumulator zeroing) ----------------
__global__ void k_class(const float* __restrict__ logits,
                        const int* __restrict__ labels) {
    int gid = blockIdx.x * 32 + threadIdx.x;
    for (int i = gid; i < NB * NROWP * NT; i += NB * NQ * 32) {
        g_dotPM[i] = 0.f; g_dotSIG[i] = 0.f;
    }
    if (gid < NB * NROWP) { g_sumSP[gid] = 0.f; g_sumSIG[gid] = 0.f; }
    if (gid < NB * NT)    { g_tsum[gid] = 0.f; }

    int b = blockIdx.x / NQ, n = blockIdx.x % NQ;
    int lane = threadIdx.x;
    __shared__ float sh[81];
    const float* L = logits + (size_t)(b * NQ + n) * 81;

    float x0 = L[lane];
    float x1 = (lane + 32 < 81) ? L[lane + 32] : -1e30f;
    float x2 = (lane + 64 < 81) ? L[lane + 64] : -1e30f;
    float m = fmaxf(x0, fmaxf(x1, x2));
    #pragma unroll
    for (int o = 16; o; o >>= 1) m = fmaxf(m, __shfl_xor_sync(0xffffffffu, m, o));

    float e0 = __expf(x0 - m);
    float e1 = (lane + 32 < 81) ? __expf(x1 - m) : 0.f;
    float e2 = (lane + 64 < 81) ? __expf(x2 - m) : 0.f;
    float s = e0 + e1 + e2;
    #pragma unroll
    for (int o = 16; o; o >>= 1) s += __shfl_xor_sync(0xffffffffu, s, o);

    sh[lane] = e0;
    if (lane + 32 < 81) sh[lane + 32] = e1;
    if (lane + 64 < 81) sh[lane + 64] = e2;
    __syncwarp();

    float inv = 1.0f / s;
    int lbl = labels[b * NT + lane];
    g_classT[(b * NT + lane) * NQ + n] = -sh[lbl] * inv;
}

// ---------------- kernel 2: target masks -> sums + B-fragments ----------------
// Pixel->k permutation: within each 16-px MMA k-tile, lane q (=lane&3) owns
// CONTIGUOUS pixels 4q..4q+3 mapped to k = {2q, 2q+1, 2q+8, 2q+9}. k_main can
// then fetch its A operand as a single float4 per row.
__global__ __launch_bounds__(256) void k_tmask(const float* __restrict__ tgt) {
    __shared__ uint32_t sbits[512];
    const int b = blockIdx.y;
    const int tid = threadIdx.x;
    int p0 = blockIdx.x * 512 + tid * 2;
    int h = p0 >> 8, w = p0 & 255;
    size_t base = ((size_t)b * NT) * 262144 + (size_t)(2 * h) * 512 + 2 * w;
    uint32_t w0 = 0, w1 = 0;
    #pragma unroll
    for (int t = 0; t < 32; ++t) {
        float4 v = __ldcs((const float4*)(tgt + base + (size_t)t * 262144));
        w0 |= (uint32_t)(v.x != 0.0f) << t;
        w1 |= (uint32_t)(v.z != 0.0f) << t;
    }
    sbits[tid * 2]     = w0;
    sbits[tid * 2 + 1] = w1;

    int lane = tid & 31;
    int cnt = 0;
    #pragma unroll
    for (int t = 0; t < 32; ++t) {
        unsigned m0 = __ballot_sync(0xffffffffu, (w0 >> t) & 1u);
        unsigned m1 = __ballot_sync(0xffffffffu, (w1 >> t) & 1u);
        if (lane == t) cnt = __popc(m0) + __popc(m1);
    }
    atomicAdd(&g_tsum[b * NT + lane], (float)cnt);
    __syncthreads();

    const int warp = tid >> 5;
    const int q4 = (lane & 3) << 2, rq = lane >> 2;   // contiguous 4-px group
    #pragma unroll
    for (int i = 0; i < 4; ++i) {
        int ktl = warp * 4 + i;
        uint32_t t0 = sbits[ktl * 16 + q4]     >> rq;  // pixel 4q   -> k=2q
        uint32_t t1 = sbits[ktl * 16 + q4 + 1] >> rq;  // pixel 4q+1 -> k=2q+1
        uint32_t t2 = sbits[ktl * 16 + q4 + 2] >> rq;  // pixel 4q+2 -> k=2q+8
        uint32_t t3 = sbits[ktl * 16 + q4 + 3] >> rq;  // pixel 4q+3 -> k=2q+9
        uint4 lo, hi;
        lo.x = ((t0 & 1u) * 0x3F80u)         | ((t1 & 1u) * 0x3F800000u);
        lo.y = ((t2 & 1u) * 0x3F80u)         | ((t3 & 1u) * 0x3F800000u);
        lo.z = (((t0 >> 8) & 1u) * 0x3F80u)  | (((t1 >> 8) & 1u) * 0x3F800000u);
        lo.w = (((t2 >> 8) & 1u) * 0x3F80u)  | (((t3 >> 8) & 1u) * 0x3F800000u);
        hi.x = (((t0 >> 16) & 1u) * 0x3F80u) | (((t1 >> 16) & 1u) * 0x3F800000u);
        hi.y = (((t2 >> 16) & 1u) * 0x3F80u) | (((t3 >> 16) & 1u) * 0x3F800000u);
        hi.z = (((t0 >> 24) & 1u) * 0x3F80u) | (((t1 >> 24) & 1u) * 0x3F800000u);
        hi.w = (((t2 >> 24) & 1u) * 0x3F80u) | (((t3 >> 24) & 1u) * 0x3F800000u);
        int kt = blockIdx.x * 32 + ktl;
        uint4* dst = g_bfrag + ((size_t)(b * NKT + kt) * 32 + lane) * 2;
        dst[0] = lo;
        dst[1] = hi;
    }
}

// ---------------- kernel 3: bf16x2 elementwise + MMA, float4 A-loads ---------
__global__ __launch_bounds__(256) void k_main(const float* __restrict__ pm) {
    __shared__ float sPM[16 * 32];
    __shared__ float sSG[16 * 32];
    __shared__ float sSP[16];
    __shared__ float sSS[16];

    const int b = blockIdx.z, mt = blockIdx.y;
    const int tid = threadIdx.x;
    const int warp = tid >> 5, lane = tid & 31;
    const int kstart = blockIdx.x * (HW / 8) + warp * (HW / 8 / 8);  // 1024 px/warp
    const int rq = lane >> 2;
    const int q4 = (lane & 3) << 2;                 // contiguous pixel group
    const int kq = (lane & 3) << 1;                 // k-quad for writeback cols
    const int r_lo = mt * 16 + rq, r_hi = r_lo + 8;
    const int rl = min(r_lo, NQ - 1), rh = min(r_hi, NQ - 1);

    for (int i = tid; i < 512; i += 256) { sPM[i] = 0.f; sSG[i] = 0.f; }
    if (tid < 16) { sSP[tid] = 0.f; sSS[tid] = 0.f; }
    __syncthreads();

    const float* pmb = pm + (size_t)b * NQ * HW;
    const uint4* bf  = g_bfrag + ((size_t)(b * NKT + (kstart >> 4)) * 32 + lane) * 2;

    const uint32_t HALF2  = 0x3F003F00u;
    const uint32_t NHALF2 = 0xBF00BF00u;
    const uint32_t ONES2  = 0x3F803F80u;

    float cpm[4][4], csg[4][4], csum[4];
    #pragma unroll
    for (int i = 0; i < 4; ++i) {
        csum[i] = 0.f;
        #pragma unroll
        for (int j = 0; j < 4; ++j) { cpm[i][j] = 0.f; csg[i][j] = 0.f; }
    }
    float splog0 = 0.f, splog1 = 0.f;

    #pragma unroll 4
    for (int it = 0; it < 64; ++it) {
        int k0 = kstart + it * 16 + q4;
        float4 xl = __ldcs((const float4*)(pmb + (size_t)rl * HW + k0));  // row lo, 4 px
        float4 xh = __ldcs((const float4*)(pmb + (size_t)rh * HW + k0));  // row hi, 4 px
        uint4 blo = bf[it * 64];
        uint4 bhi = bf[it * 64 + 1];

        // A fragment: a0=(rl,k2q..2q+1)=px(4q,4q+1); a2=(rl,k+8)=px(4q+2,4q+3)
        uint32_t apm[4] = { pack_bf16(xl.y, xl.x), pack_bf16(xh.y, xh.x),
                            pack_bf16(xl.w, xl.z), pack_bf16(xh.w, xh.z) };

        uint32_t asg[4], aq[4];
        #pragma unroll
        for (int q = 0; q < 4; ++q) {
            uint32_t th;
            asm("mul.rn.bf16x2 %0, %1, %2;" : "=r"(th) : "r"(apm[q]), "r"(HALF2));
            asm("tanh.approx.bf16x2 %0, %1;" : "=r"(th) : "r"(th));
            asm("fma.rn.bf16x2 %0, %1, %2, %3;" : "=r"(asg[q]) : "r"(th), "r"(HALF2),  "r"(HALF2));
            asm("fma.rn.bf16x2 %0, %1, %2, %3;" : "=r"(aq[q])  : "r"(th), "r"(NHALF2), "r"(HALF2));
        }

        // softplus row sums: product of the 4 per-row sigmoid(-x), one log each
        uint32_t prL, prH;
        asm("mul.rn.bf16x2 %0, %1, %2;" : "=r"(prL) : "r"(aq[0]), "r"(aq[2]));
        asm("mul.rn.bf16x2 %0, %1, %2;" : "=r"(prH) : "r"(aq[1]), "r"(aq[3]));
        float fL = __uint_as_float(prL << 16) * __uint_as_float(prL & 0xFFFF0000u);
        float fH = __uint_as_float(prH << 16) * __uint_as_float(prH & 0xFFFF0000u);
        splog0 += __logf(fL);
        splog1 += __logf(fH);

        mma_bf16(cpm[0], apm, blo.x, blo.y);
        mma_bf16(csg[0], asg, blo.x, blo.y);
        mma_bf16(cpm[1], apm, blo.z, blo.w);
        mma_bf16(csg[1], asg, blo.z, blo.w);
        mma_bf16(cpm[2], apm, bhi.x, bhi.y);
        mma_bf16(csg[2], asg, bhi.x, bhi.y);
        mma_bf16(cpm[3], apm, bhi.z, bhi.w);
        mma_bf16(csg[3], asg, bhi.z, bhi.w);
        mma_bf16(csum,   asg, ONES2, ONES2);
    }

    #pragma unroll
    for (int nt = 0; nt < 4; ++nt) {
        int c = nt * 8 + kq;
        atomicAdd(&sPM[rq * 32 + c],           cpm[nt][0]);
        atomicAdd(&sPM[rq * 32 + c + 1],       cpm[nt][1]);
        atomicAdd(&sPM[(rq + 8) * 32 + c],     cpm[nt][2]);
        atomicAdd(&sPM[(rq + 8) * 32 + c + 1], cpm[nt][3]);
        atomicAdd(&sSG[rq * 32 + c],           csg[nt][0]);
        atomicAdd(&sSG[rq * 32 + c + 1],       csg[nt][1]);
        atomicAdd(&sSG[(rq + 8) * 32 + c],     csg[nt][2]);
        atomicAdd(&sSG[(rq + 8) * 32 + c + 1], csg[nt][3]);
    }
    atomicAdd(&sSP[rq],     -splog0);
    atomicAdd(&sSP[rq + 8], -splog1);
    if (kq == 0) {
        atomicAdd(&sSS[rq],     csum[0]);
        atomicAdd(&sSS[rq + 8], csum[2]);
    }
    __syncthreads();

    for (int i = tid; i < 512; i += 256) {
        int r = i >> 5, c = i & 31;
        int grow = mt * 16 + r;
        atomicAdd(&g_dotPM[(b * NROWP + grow) * NT + c],  sPM[i]);
        atomicAdd(&g_dotSIG[(b * NROWP + grow) * NT + c], sSG[i]);
    }
    if (tid < 16) {
        int grow = mt * 16 + tid;
        atomicAdd(&g_sumSP[b * NROWP + grow],  sSP[tid]);
        atomicAdd(&g_sumSIG[b * NROWP + grow], sSS[tid]);
    }
}

// ---------------- kernel 4: cost assembly + branchless JV -------------------
__global__ __launch_bounds__(128) void k_hung(float* __restrict__ out) {
    const int b = blockIdx.x;
    const int tid = threadIdx.x;
    const int lane = tid & 31;
    __shared__ float CsBuf[NT * NQ + 40];   // +1 front pad, +tail pad
    __shared__ float u[NT + 1];
    __shared__ float ucol[NQ + 1];
    __shared__ int   psh[NQ + 1];
    float* Cs = CsBuf + 1;

    for (int idx = tid; idx < NT * NQ; idx += 128) {
        int t = idx / NQ, n = idx - t * NQ;
        float spm  = g_sumSP[b * NROWP + n] * (1.0f / HW);
        float dpm  = g_dotPM[(b * NROWP + n) * NT + t] * (1.0f / HW);
        float dsg  = g_dotSIG[(b * NROWP + n) * NT + t];
        float den  = g_sumSIG[b * NROWP + n] + g_tsum[b * NT + t] + 1.0f;
        float dice = 1.0f - __fdividef(2.0f * dsg + 1.0f, den);
        Cs[idx] = g_classT[b * NT * NQ + idx] + (spm - dpm) + dice;
    }
    for (int j = tid; j <= NQ; j += 128) psh[j] = 0;
    __syncthreads();
    if (tid >= 32) return;

    float v0 = 0.f, v1 = 0.f, v2 = 0.f, v3 = 0.f;
    int   p0 = 0, p1 = 0, p2 = 0, p3 = 0;
    int   w0 = 0, w1 = 0, w2 = 0, w3 = 0;

    // ---- greedy init ----
    uint32_t cm0 = 1u, cm1 = 0, cm2 = 0, cm3 = 0;
    uint32_t freerows = 0;
    for (int i = 1; i <= NT; ++i) {
        const float* Crow = Cs + (i - 1) * NQ;
        uint32_t k0 = (fkey(Crow[lane - 1]) & ~127u) | lane;
        k0 = (lane >= 1) ? k0 : 0xFFFFFFFFu;
        uint32_t k1 = (fkey(Crow[31 + lane]) & ~127u) | (32 + lane);
        uint32_t k2 = (fkey(Crow[63 + lane]) & ~127u) | (64 + lane);
        uint32_t k3 = (fkey(Crow[95 + lane]) & ~127u) | (96 + lane);
        k3 = (lane <= 4) ? k3 : 0xFFFFFFFFu;
        uint32_t bk = min(min(k0, k1), min(k2, k3));
        uint32_t kmin = __reduce_min_sync(0xffffffffu, bk);
        int js = kmin & 127;
        float ui = fkey_inv(kmin & ~127u);
        if (lane == 0) u[i] = ui;
        int slot = js >> 5;
        uint32_t bit = 1u << (js & 31);
        uint32_t cm = slot == 0 ? cm0 : slot == 1 ? cm1 : slot == 2 ? cm2 : cm3;
        if (!(cm & bit)) {
            if ((js & 31) == lane) {
                if (slot == 0) p0 = i; else if (slot == 1) p1 = i;
                else if (slot == 2) p2 = i; else p3 = i;
                psh[js] = i;
                ucol[js] = ui;
            }
            if (slot == 0) cm0 |= bit; else if (slot == 1) cm1 |= bit;
            else if (slot == 2) cm2 |= bit; else cm3 |= bit;
        } else {
            freerows |= 1u << (i - 1);
        }
    }
    __syncwarp();

    // ---- Dijkstra phases: branchless inner loop, lazy dual updates ----
    while (freerows) {
        int i = __ffs(freerows);
        freerows &= freerows - 1;
        float m0 = 1e30f, m1 = 1e30f, m2 = 1e30f, m3 = 1e30f;
        float dj0 = 0.f, dj1r = 0.f, dj2 = 0.f, dj3 = 0.f;
        float D = 0.f;
        unsigned usedm = 0;
        if (lane == 0) p0 = i;
        int j0 = 0, i0 = i;
        float ui0 = u[i];

        while (true) {
            unsigned joined = ((j0 & 31) == lane) ? (1u << (j0 >> 5)) : 0u;
            dj0  = (joined & 1u) ? D : dj0;
            dj1r = (joined & 2u) ? D : dj1r;
            dj2  = (joined & 4u) ? D : dj2;
            dj3  = (joined & 8u) ? D : dj3;
            usedm |= joined;

            const float* Cr = Cs + (i0 - 1) * NQ;
            float s0 = ui0 + v0, s1 = ui0 + v1, s2 = ui0 + v2, s3 = ui0 + v3;

            bool a0 = (lane >= 1) && !(usedm & 1u);
            bool a1 = !(usedm & 2u);
            bool a2 = !(usedm & 4u);
            bool a3 = (lane <= 4) && !(usedm & 8u);

            float c0 = Cr[lane - 1]  - s0;  c0 = a0 ? c0 : 1e30f;
            float c1 = Cr[31 + lane] - s1;  c1 = a1 ? c1 : 1e30f;
            float c2 = Cr[63 + lane] - s2;  c2 = a2 ? c2 : 1e30f;
            float c3 = Cr[95 + lane] - s3;  c3 = a3 ? c3 : 1e30f;

            bool b0 = c0 < m0; w0 = b0 ? j0 : w0; m0 = b0 ? c0 : m0;
            bool b1 = c1 < m1; w1 = b1 ? j0 : w1; m1 = b1 ? c1 : m1;
            bool b2 = c2 < m2; w2 = b2 ? j0 : w2; m2 = b2 ? c2 : m2;
            bool b3 = c3 < m3; w3 = b3 ? j0 : w3; m3 = b3 ? c3 : m3;

            uint32_t k0 = (fkey(m0) & ~127u) | lane;        k0 = a0 ? k0 : 0xFFFFFFFFu;
            uint32_t k1 = (fkey(m1) & ~127u) | (32 + lane); k1 = a1 ? k1 : 0xFFFFFFFFu;
            uint32_t k2 = (fkey(m2) & ~127u) | (64 + lane); k2 = a2 ? k2 : 0xFFFFFFFFu;
            uint32_t k3 = (fkey(m3) & ~127u) | (96 + lane); k3 = a3 ? k3 : 0xFFFFFFFFu;
            uint32_t bk = min(min(k0, k1), min(k2, k3));

            uint32_t kmin = __reduce_min_sync(0xffffffffu, bk);
            float delta = fkey_inv(kmin & ~127u);
            int j1 = kmin & 127;

            int   pj1 = psh[j1];
            float uc1 = ucol[j1];

            m0 -= (usedm & 1u) ? 0.f : delta;
            m1 -= (usedm & 2u) ? 0.f : delta;
            m2 -= (usedm & 4u) ? 0.f : delta;
            m3 -= (usedm & 8u) ? 0.f : delta;
            D += delta;

            j0 = j1;
            if (pj1 == 0) break;
            i0 = pj1;
            ui0 = uc1;
        }

        if (usedm & 1u) { float t = D - dj0;  v0 -= t; u[p0] += t; ucol[lane] += t; }
        if (usedm & 2u) { float t = D - dj1r; v1 -= t; u[p1] += t; ucol[32 + lane] += t; }
        if (usedm & 4u) { float t = D - dj2;  v2 -= t; u[p2] += t; ucol[64 + lane] += t; }
        if (usedm & 8u) { float t = D - dj3;  v3 -= t; u[p3] += t; ucol[96 + lane] += t; }
        __syncwarp();

        while (j0 != 0) {
            int j1  = __shfl_sync(0xffffffffu, sel4i(w0, w1, w2, w3, j0 >> 5), j0 & 31);
            int pj1 = (j1 == 0) ? i : psh[j1];
            if ((j0 & 31) == lane) {
                int s = j0 >> 5;
                if (s == 0) p0 = pj1; else if (s == 1) p1 = pj1;
                else if (s == 2) p2 = pj1; else p3 = pj1;
                psh[j0] = pj1;
                ucol[j0] = u[pj1];
            }
            j0 = j1;
            __syncwarp();
        }
        __syncwarp();
    }

    // parallel emit
    int base = 0;
    #pragma unroll
    for (int c = 0; c < 4; ++c) {
        int j = c * 32 + lane + 1;
        bool m = (j <= NQ) && (psh[j] != 0);
        unsigned ball = __ballot_sync(0xffffffffu, m);
        if (m) {
            int k = base + __popc(ball & ((1u << lane) - 1u));
            out[b * NT + k]           = (float)(j - 1);
            out[NB * NT + b * NT + k] = (float)(psh[j] - 1);
        }
        base += __popc(ball);
    }
}

// ---------------- launch ----------------
extern "C" void kernel_launch(void* const* d_in, const int* in_sizes, int n_in,
                              void* d_out, int out_size) {
    const float* logits = nullptr;
    const float* pmask  = nullptr;
    const float* tmask  = nullptr;
    const int*   labels = nullptr;

    for (int i = 0; i < n_in; ++i) {
        switch (in_sizes[i]) {
            case 64800:    logits = (const float*)d_in[i]; break;
            case 52428800: pmask  = (const float*)d_in[i]; break;
            case 256:      labels = (const int*)d_in[i];   break;
            default:
                if (in_sizes[i] == 67108864) tmask = (const float*)d_in[i];
                break;
        }
    }
    float* out = (float*)d_out;

    k_class<<<NB * NQ, 32>>>(logits, labels);
    k_tmask<<<dim3(HW / 512, NB), 256>>>(tmask);
    k_main<<<dim3(8, 7, NB), 256>>>(pmask);
    k_hung<<<NB, 128>>>(out);
}